// round 1
// baseline (speedup 1.0000x reference)
#include <cuda_runtime.h>
#include <math.h>

#define B_ 2
#define H_ 8
#define NSEQ 2048
#define DDIM 64
#define BH (B_*H_)
#define ROWS 8
#define NTHREADS 256
#define TILE_M 64
#define PAD 68            // 64 + 4 floats: conflict-free LDS.128 across lanes
#define NWORDS 3126       // ceil(100001 / 32)

// smem layout sizes (floats / words)
#define QS_F   (ROWS*DDIM)          // 512 floats
#define S_F    (ROWS*NSEQ)          // 16384 floats
#define TILE_F (TILE_M*PAD)         // 4352 floats
#define BMP_W  3128                 // padded word count

__global__ __launch_bounds__(NTHREADS, 2)
void sdpa_dedup_kernel(const float* __restrict__ q,
                       const float* __restrict__ k,
                       const float* __restrict__ v,
                       float* __restrict__ out,
                       float* __restrict__ attn_out) {
    extern __shared__ unsigned char smem_raw[];
    float* qs   = (float*)smem_raw;                       // [ROWS][DDIM], pre-scaled by 1/T
    float* s    = qs + QS_F;                              // [ROWS][NSEQ] scores -> rounded ints (as float)
    float* tile = s + S_F;                                // [TILE_M][PAD] K/V tile
    unsigned* bmp = (unsigned*)(tile + TILE_F);           // presence bitmap
    unsigned long long* totSum = (unsigned long long*)(bmp + BMP_W);
    float* scaleArr = (float*)(totSum + 2);               // [ROWS] 1/denom_int

    const int tid  = threadIdx.x;
    const int w    = tid >> 5;     // warp id == row within tile
    const int lane = tid & 31;
    const int bh   = blockIdx.y;
    const int row0 = blockIdx.x * ROWS;
    const size_t base = (size_t)bh * NSEQ * DDIM;

    // ---- load Q tile, pre-scaled by 1/TEMPERATURE ----
    for (int i = tid; i < ROWS*DDIM; i += NTHREADS)
        qs[i] = q[base + (size_t)row0*DDIM + i] * 0.125f;
    __syncthreads();

    // ---- phase 1: scores S = (Q/T) @ K^T ----
    for (int t = 0; t < NSEQ/TILE_M; t++) {
        const float4* kg = (const float4*)(k + base + (size_t)t*TILE_M*DDIM);
        for (int i = tid; i < TILE_M*DDIM/4; i += NTHREADS) {
            int rm = i >> 4, c4 = i & 15;
            *(float4*)&tile[rm*PAD + c4*4] = kg[i];
        }
        __syncthreads();
        const float4* qrow = (const float4*)&qs[w*DDIM];
        #pragma unroll
        for (int mi = 0; mi < 2; mi++) {
            int ml = lane + mi*32;
            const float4* krow = (const float4*)&tile[ml*PAD];
            float acc = 0.0f;
            #pragma unroll
            for (int d4 = 0; d4 < 16; d4++) {
                float4 qv = qrow[d4];
                float4 kv = krow[d4];
                acc += qv.x*kv.x + qv.y*kv.y + qv.z*kv.z + qv.w*kv.w;
            }
            s[w*NSEQ + t*TILE_M + ml] = acc;
        }
        __syncthreads();
    }

    // ---- phase 2: row max (warp w owns row w; each lane touches only m%32==lane,
    //      which it wrote itself, so no extra sync needed) ----
    float mx = -INFINITY;
    for (int m = lane; m < NSEQ; m += 32) mx = fmaxf(mx, s[w*NSEQ + m]);
    #pragma unroll
    for (int o = 16; o > 0; o >>= 1) mx = fmaxf(mx, __shfl_xor_sync(0xffffffffu, mx, o));

    // ---- phase 3: exp + round-half-even to 5 decimals; keep integer value as float ----
    for (int m = lane; m < NSEQ; m += 32) {
        float e = expf(s[w*NSEQ + m] - mx);
        s[w*NSEQ + m] = rintf(e * 100000.0f);   // integer in [0, 100000], exact in f32
    }
    __syncthreads();

    // ---- phase 4: per-row distinct-sum denominator via presence bitmap ----
    for (int r = 0; r < ROWS; r++) {
        for (int i = tid; i < NWORDS; i += NTHREADS) bmp[i] = 0u;
        if (tid == 0) *totSum = 0ull;
        __syncthreads();
        for (int m = tid; m < NSEQ; m += NTHREADS) {
            int ri = (int)s[r*NSEQ + m];
            atomicOr(&bmp[ri >> 5], 1u << (ri & 31));
        }
        __syncthreads();
        unsigned long long ls = 0ull;
        for (int i = tid; i < NWORDS; i += NTHREADS) {
            unsigned bits = bmp[i];
            if (bits) {
                ls += (unsigned long long)((unsigned)i * 32u) * (unsigned)__popc(bits);
                while (bits) { ls += (unsigned)(__ffs(bits) - 1); bits &= bits - 1u; }
            }
        }
        #pragma unroll
        for (int o = 16; o > 0; o >>= 1) ls += __shfl_xor_sync(0xffffffffu, ls, o);
        if (lane == 0) atomicAdd(totSum, ls);
        __syncthreads();
        if (tid == 0) scaleArr[r] = 1.0f / (float)(*totSum);  // p = r_int / sum_int
        __syncthreads();
    }

    // ---- phase 5a: write attn_p row (warp w -> row w), coalesced float4 ----
    {
        float sc = scaleArr[w];
        float4* dst4 = (float4*)(attn_out + ((size_t)bh*NSEQ + row0 + w) * NSEQ);
        const float4* src4 = (const float4*)&s[w*NSEQ];
        for (int i = lane; i < NSEQ/4; i += 32) {
            float4 vv = src4[i];
            vv.x *= sc; vv.y *= sc; vv.z *= sc; vv.w *= sc;
            dst4[i] = vv;
        }
    }

    // ---- phase 5b: output = attn_p @ V (accumulate with raw ints, scale at end) ----
    float acc0 = 0.0f, acc1 = 0.0f;
    for (int t = 0; t < NSEQ/TILE_M; t++) {
        __syncthreads();   // previous tile consumers done
        const float4* vg = (const float4*)(v + base + (size_t)t*TILE_M*DDIM);
        for (int i = tid; i < TILE_M*DDIM/4; i += NTHREADS) {
            int rm = i >> 4, c4 = i & 15;
            *(float4*)&tile[rm*PAD + c4*4] = vg[i];
        }
        __syncthreads();
        const float* srow = &s[w*NSEQ + t*TILE_M];
        #pragma unroll 8
        for (int mm = 0; mm < TILE_M; mm++) {
            float p = srow[mm];               // warp-uniform broadcast
            acc0 += p * tile[mm*PAD + lane];
            acc1 += p * tile[mm*PAD + lane + 32];
        }
    }
    {
        float sc = scaleArr[w];
        float* orow = out + ((size_t)bh*NSEQ + row0 + w) * DDIM;
        orow[lane]      = acc0 * sc;
        orow[lane + 32] = acc1 * sc;
    }
}

extern "C" void kernel_launch(void* const* d_in, const int* in_sizes, int n_in,
                              void* d_out, int out_size) {
    const float* q = (const float*)d_in[0];
    const float* k = (const float*)d_in[1];
    const float* v = (const float*)d_in[2];
    float* out = (float*)d_out;                                   // [B,H,N,D]
    float* attn_out = out + (size_t)B_ * H_ * NSEQ * DDIM;        // [B,H,N,N]

    const int smem_bytes = (QS_F + S_F + TILE_F) * 4 + BMP_W * 4 + 16 + ROWS * 4;
    cudaFuncSetAttribute(sdpa_dedup_kernel,
                         cudaFuncAttributeMaxDynamicSharedMemorySize, smem_bytes);

    dim3 grid(NSEQ / ROWS, BH);
    sdpa_dedup_kernel<<<grid, NTHREADS, smem_bytes>>>(q, k, v, out, attn_out);
}

// round 2
// speedup vs baseline: 2.0290x; 2.0290x over previous
#include <cuda_runtime.h>
#include <math.h>

#define B_ 2
#define H_ 8
#define NSEQ 2048
#define DDIM 64
#define BH (B_*H_)
#define ROWS 16
#define NTHREADS 256
#define TILE_M 64
#define PAD 68            // 64 + 4 floats: conflict-free row-per-lane LDS.128
#define NTILES (NSEQ/TILE_M)
#define NWORDS 3126       // ceil(100001 / 32)
#define BMP_W  3128
#define TILE_F (TILE_M*PAD)

typedef unsigned long long u64;

__device__ __forceinline__ u64 pk2(float x, float y) {
    u64 u; asm("mov.b64 %0,{%1,%2};" : "=l"(u) : "f"(x), "f"(y)); return u;
}
__device__ __forceinline__ float2 up2(u64 u) {
    float2 r; asm("mov.b64 {%0,%1},%2;" : "=f"(r.x), "=f"(r.y) : "l"(u)); return r;
}
__device__ __forceinline__ void fma2(u64 &d, u64 a, u64 b) {
    asm("fma.rn.f32x2 %0,%1,%2,%3;" : "=l"(d) : "l"(a), "l"(b), "l"(d));
}

__global__ __launch_bounds__(NTHREADS, 1)
void sdpa_dedup_kernel(const float* __restrict__ q,
                       const float* __restrict__ k,
                       const float* __restrict__ v,
                       float* __restrict__ out,
                       float* __restrict__ attn_out) {
    extern __shared__ float sm[];
    float* s    = sm;                               // [ROWS][NSEQ] scores -> rounded ints
    float* qs   = s + ROWS*NSEQ;                    // [ROWS][DDIM] pre-scaled Q
    float* tile = qs + ROWS*DDIM;                   // 2 x [TILE_M][PAD] K/V double buffer
    float* part = tile + 2*TILE_F;                  // [8][ROWS][DDIM] PV partials
    unsigned* bmp = (unsigned*)(part + 8*ROWS*DDIM);
    u64* rowSum = (u64*)(bmp + BMP_W);              // [ROWS]
    float* scale = (float*)(rowSum + ROWS);         // [ROWS]

    const int tid  = threadIdx.x;
    const int w    = tid >> 5;
    const int lane = tid & 31;
    const int qg   = w >> 1;        // 0..3 -> q-rows [4qg, 4qg+4)
    const int kg   = w & 1;         // 0/1  -> k-col half
    const int bh   = blockIdx.y;
    const int row0 = blockIdx.x * ROWS;
    const size_t base = (size_t)bh * NSEQ * DDIM;

    // ---- init: load Q (pre-scaled by 1/T), clear bitmap + row sums ----
    for (int i = tid; i < ROWS*DDIM; i += NTHREADS)
        qs[i] = q[base + (size_t)row0*DDIM + i] * 0.125f;
    for (int i = tid; i < NWORDS; i += NTHREADS) bmp[i] = 0u;
    if (tid < ROWS) rowSum[tid] = 0ull;

    // fill K tile 0
    {
        const float4* kg4 = (const float4*)(k + base);
        for (int i = tid; i < TILE_M*DDIM/4; i += NTHREADS) {
            int rm = i >> 4, c4 = i & 15;
            *(float4*)&tile[rm*PAD + c4*4] = kg4[i];
        }
    }
    __syncthreads();

    // ---- phase 1: S = (Q/T) @ K^T  (4 q-rows per warp, half k-cols per warp) ----
    const float4* qs4 = (const float4*)qs;
    for (int t = 0; t < NTILES; t++) {
        float4 pre0, pre1, pre2, pre3;
        if (t + 1 < NTILES) {
            const float4* kg4 = (const float4*)(k + base + (size_t)(t+1)*TILE_M*DDIM);
            pre0 = kg4[tid];            pre1 = kg4[tid + NTHREADS];
            pre2 = kg4[tid + 2*NTHREADS]; pre3 = kg4[tid + 3*NTHREADS];
        }
        const float4* krow = (const float4*)&tile[(t&1)*TILE_F + (kg*32 + lane)*PAD];
        u64 a0 = 0, a1 = 0, a2 = 0, a3 = 0;
        #pragma unroll
        for (int d4 = 0; d4 < 16; d4++) {
            float4 kv = krow[d4];
            u64 kl = pk2(kv.x, kv.y), kh = pk2(kv.z, kv.w);
            float4 qv;
            qv = qs4[(4*qg+0)*16 + d4]; fma2(a0, pk2(qv.x,qv.y), kl); fma2(a0, pk2(qv.z,qv.w), kh);
            qv = qs4[(4*qg+1)*16 + d4]; fma2(a1, pk2(qv.x,qv.y), kl); fma2(a1, pk2(qv.z,qv.w), kh);
            qv = qs4[(4*qg+2)*16 + d4]; fma2(a2, pk2(qv.x,qv.y), kl); fma2(a2, pk2(qv.z,qv.w), kh);
            qv = qs4[(4*qg+3)*16 + d4]; fma2(a3, pk2(qv.x,qv.y), kl); fma2(a3, pk2(qv.z,qv.w), kh);
        }
        int m = t*TILE_M + kg*32 + lane;
        float2 f;
        f = up2(a0); s[(4*qg+0)*NSEQ + m] = f.x + f.y;
        f = up2(a1); s[(4*qg+1)*NSEQ + m] = f.x + f.y;
        f = up2(a2); s[(4*qg+2)*NSEQ + m] = f.x + f.y;
        f = up2(a3); s[(4*qg+3)*NSEQ + m] = f.x + f.y;
        if (t + 1 < NTILES) {
            float* dst = &tile[((t+1)&1)*TILE_F];
            int i0 = tid, i1 = tid+NTHREADS, i2 = tid+2*NTHREADS, i3 = tid+3*NTHREADS;
            *(float4*)&dst[(i0>>4)*PAD + (i0&15)*4] = pre0;
            *(float4*)&dst[(i1>>4)*PAD + (i1&15)*4] = pre1;
            *(float4*)&dst[(i2>>4)*PAD + (i2&15)*4] = pre2;
            *(float4*)&dst[(i3>>4)*PAD + (i3&15)*4] = pre3;
        }
        __syncthreads();
    }

    // ---- phase 2+3: per-row max, exp, round (warp w owns rows 2w, 2w+1) ----
    {
        const int r0 = 2*w, r1 = 2*w + 1;
        float mx0 = -INFINITY, mx1 = -INFINITY;
        for (int m = lane; m < NSEQ; m += 32) {
            mx0 = fmaxf(mx0, s[r0*NSEQ + m]);
            mx1 = fmaxf(mx1, s[r1*NSEQ + m]);
        }
        #pragma unroll
        for (int o = 16; o > 0; o >>= 1) {
            mx0 = fmaxf(mx0, __shfl_xor_sync(0xffffffffu, mx0, o));
            mx1 = fmaxf(mx1, __shfl_xor_sync(0xffffffffu, mx1, o));
        }
        for (int m = lane; m < NSEQ; m += 32) {
            s[r0*NSEQ + m] = rintf(expf(s[r0*NSEQ + m] - mx0) * 100000.0f);
            s[r1*NSEQ + m] = rintf(expf(s[r1*NSEQ + m] - mx1) * 100000.0f);
        }
    }
    __syncthreads();

    // ---- phase 4: distinct-sum denominator per row (first-setter detection) ----
    for (int r = 0; r < ROWS; r++) {
        u64 local = 0ull;
        for (int m = tid; m < NSEQ; m += NTHREADS) {
            int ri = (int)s[r*NSEQ + m];
            unsigned bit = 1u << (ri & 31);
            unsigned old = atomicOr(&bmp[ri >> 5], bit);
            if (!(old & bit)) local += (unsigned)ri;
        }
        #pragma unroll
        for (int o = 16; o > 0; o >>= 1) local += __shfl_xor_sync(0xffffffffu, local, o);
        if (lane == 0 && local) atomicAdd(&rowSum[r], local);
        __syncthreads();
        // clear only touched words
        for (int m = tid; m < NSEQ; m += NTHREADS)
            bmp[((int)s[r*NSEQ + m]) >> 5] = 0u;
        __syncthreads();
    }
    if (tid < ROWS) scale[tid] = 1.0f / (float)rowSum[tid];
    __syncthreads();

    // ---- phase 5a: write attn_p (warp w -> rows 2w, 2w+1), coalesced float4 ----
    {
        #pragma unroll
        for (int rr = 0; rr < 2; rr++) {
            int r = 2*w + rr;
            float sc = scale[r];
            float4* dst4 = (float4*)(attn_out + ((size_t)bh*NSEQ + row0 + r) * NSEQ);
            const float4* src4 = (const float4*)&s[r*NSEQ];
            for (int i = lane; i < NSEQ/4; i += 32) {
                float4 vv = src4[i];
                vv.x *= sc; vv.y *= sc; vv.z *= sc; vv.w *= sc;
                dst4[i] = vv;
            }
        }
    }

    // ---- phase 5b: PV. Warps split m-range; each V element feeds all 16 rows ----
    // fill V tile 0
    {
        const float4* vg4 = (const float4*)(v + base);
        for (int i = tid; i < TILE_M*DDIM/4; i += NTHREADS) {
            int rm = i >> 4, c4 = i & 15;
            *(float4*)&tile[rm*PAD + c4*4] = vg4[i];
        }
    }
    __syncthreads();

    u64 acc[ROWS];
    #pragma unroll
    for (int r = 0; r < ROWS; r++) acc[r] = 0ull;

    for (int t = 0; t < NTILES; t++) {
        float4 pre0, pre1, pre2, pre3;
        if (t + 1 < NTILES) {
            const float4* vg4 = (const float4*)(v + base + (size_t)(t+1)*TILE_M*DDIM);
            pre0 = vg4[tid];              pre1 = vg4[tid + NTHREADS];
            pre2 = vg4[tid + 2*NTHREADS]; pre3 = vg4[tid + 3*NTHREADS];
        }
        const float* tb = &tile[(t&1)*TILE_F];
        #pragma unroll
        for (int g = 0; g < 2; g++) {
            int j0 = w*8 + g*4;          // m offset within tile
            float2 v0 = *(const float2*)&tb[(j0+0)*PAD + 2*lane];
            float2 v1 = *(const float2*)&tb[(j0+1)*PAD + 2*lane];
            float2 v2 = *(const float2*)&tb[(j0+2)*PAD + 2*lane];
            float2 v3 = *(const float2*)&tb[(j0+3)*PAD + 2*lane];
            u64 vv0 = pk2(v0.x, v0.y), vv1 = pk2(v1.x, v1.y);
            u64 vv2 = pk2(v2.x, v2.y), vv3 = pk2(v3.x, v3.y);
            int m0 = t*TILE_M + j0;
            #pragma unroll
            for (int r = 0; r < ROWS; r++) {
                float4 p = *(const float4*)&s[r*NSEQ + m0];
                fma2(acc[r], pk2(p.x, p.x), vv0);
                fma2(acc[r], pk2(p.y, p.y), vv1);
                fma2(acc[r], pk2(p.z, p.z), vv2);
                fma2(acc[r], pk2(p.w, p.w), vv3);
            }
        }
        if (t + 1 < NTILES) {
            float* dst = &tile[((t+1)&1)*TILE_F];
            int i0 = tid, i1 = tid+NTHREADS, i2 = tid+2*NTHREADS, i3 = tid+3*NTHREADS;
            *(float4*)&dst[(i0>>4)*PAD + (i0&15)*4] = pre0;
            *(float4*)&dst[(i1>>4)*PAD + (i1&15)*4] = pre1;
            *(float4*)&dst[(i2>>4)*PAD + (i2&15)*4] = pre2;
            *(float4*)&dst[(i3>>4)*PAD + (i3&15)*4] = pre3;
        }
        __syncthreads();
    }

    // store per-warp partials, then fixed-order cross-warp reduction
    #pragma unroll
    for (int r = 0; r < ROWS; r++) {
        float2 f = up2(acc[r]);
        *(float2*)&part[w*(ROWS*DDIM) + r*DDIM + 2*lane] = f;
    }
    __syncthreads();

    for (int i = tid; i < ROWS*DDIM; i += NTHREADS) {
        float o = 0.0f;
        #pragma unroll
        for (int w2 = 0; w2 < 8; w2++) o += part[w2*(ROWS*DDIM) + i];
        int r = i >> 6, c = i & 63;
        out[((size_t)bh*NSEQ + row0 + r)*DDIM + c] = o * scale[r];
    }
}

extern "C" void kernel_launch(void* const* d_in, const int* in_sizes, int n_in,
                              void* d_out, int out_size) {
    const float* q = (const float*)d_in[0];
    const float* k = (const float*)d_in[1];
    const float* v = (const float*)d_in[2];
    float* out = (float*)d_out;                                   // [B,H,N,D]
    float* attn_out = out + (size_t)B_ * H_ * NSEQ * DDIM;        // [B,H,N,N]

    const int smem_bytes = (ROWS*NSEQ + ROWS*DDIM + 2*TILE_F + 8*ROWS*DDIM) * 4
                         + BMP_W * 4 + ROWS * 8 + ROWS * 4;
    cudaFuncSetAttribute(sdpa_dedup_kernel,
                         cudaFuncAttributeMaxDynamicSharedMemorySize, smem_bytes);

    dim3 grid(NSEQ / ROWS, BH);
    sdpa_dedup_kernel<<<grid, NTHREADS, smem_bytes>>>(q, k, v, out, attn_out);
}